// round 16
// baseline (speedup 1.0000x reference)
#include <cuda_runtime.h>
#include <cuda_bf16.h>
#include <math.h>
#include <cstdint>

#define NB_ 4
#define S_ 2048
#define D_ 2048
#define H_ 16
#define DH_ 128
#define T_ (NB_*S_)

typedef unsigned long long u64;
typedef unsigned int u32;

#if !defined(__CUDA_ARCH__) || defined(__CUDA_ARCH_FEAT_SM103_ALL)
#define TC_EN 1
#else
#define TC_EN 0
#endif

// ---------------- generic helpers ----------------
__device__ __forceinline__ u32 smem_u32(const void* p) {
    u32 a;
    asm("{ .reg .u64 t; cvta.to.shared.u64 t, %1; cvt.u32.u64 %0, t; }"
        : "=r"(a) : "l"(p));
    return a;
}
__device__ __forceinline__ u32 elect1() {
    u32 p;
    asm volatile("{ .reg .pred p; elect.sync _|p, 0xFFFFFFFF; selp.b32 %0,1,0,p; }"
                 : "=r"(p));
    return p;
}
__device__ __forceinline__ u32 swz(u32 x) { return x ^ ((x >> 3) & 0x70); }
__device__ __forceinline__ u32 packbf(float x, float y) {
    u32 r; asm("cvt.rn.bf16x2.f32 %0, %1, %2;" : "=r"(r) : "f"(y), "f"(x));
    return r;
}
__device__ __forceinline__ void split8(float4 v0, float4 v1, uint4 &hi, uint4 &lo) {
    float f[8] = {v0.x, v0.y, v0.z, v0.w, v1.x, v1.y, v1.z, v1.w};
    u32 hw[4], lw[4];
#pragma unroll
    for (int j = 0; j < 4; ++j) {
        float a = f[2 * j], b = f[2 * j + 1];
        float ah = __bfloat162float(__float2bfloat16(a));
        float bh = __bfloat162float(__float2bfloat16(b));
        hw[j] = packbf(ah, bh);
        lw[j] = packbf(a - ah, b - bh);
    }
    hi = make_uint4(hw[0], hw[1], hw[2], hw[3]);
    lo = make_uint4(lw[0], lw[1], lw[2], lw[3]);
}

#define MBAR_INIT(a, c) \
    asm volatile("mbarrier.init.shared.b64 [%0], %1;" :: "r"(a), "r"(c) : "memory")

#define MBAR_WAIT(a, ph) do { \
    u32 _m = (a), _p = (ph), _d; \
    asm volatile("{\n .reg .pred p;\n" \
        " mbarrier.try_wait.parity.acquire.cta.shared::cta.b64 p, [%1], %2;\n" \
        " selp.b32 %0,1,0,p;\n}" : "=r"(_d) : "r"(_m), "r"(_p) : "memory"); \
    if (!_d) { \
        asm volatile("{\n .reg .pred P;\n" \
            "LW%=:\n mbarrier.try_wait.parity.acquire.cta.shared::cta.b64 P, [%0], %1, 0x989680;\n" \
            " @P bra.uni LD%=;\n bra.uni LW%=;\nLD%=:\n}" \
            :: "r"(_m), "r"(_p) : "memory"); \
    } \
} while (0)

#if TC_EN
#define TC_ALLOC(sa, n) \
    asm volatile("tcgen05.alloc.cta_group::1.sync.aligned.shared::cta.b32 [%0], %1;" \
                 :: "r"(sa), "r"(n) : "memory")
#define TC_RELQ() \
    asm volatile("tcgen05.relinquish_alloc_permit.cta_group::1.sync.aligned;")
#define TC_DEALLOC(t, n) \
    asm volatile("tcgen05.dealloc.cta_group::1.sync.aligned.b32 %0, %1;" :: "r"(t), "r"(n))
#define TC_COMMIT(mb) \
    asm volatile("tcgen05.commit.cta_group::1.mbarrier::arrive::one.shared::cluster.b64 [%0];" \
                 :: "r"(mb) : "memory")
#define TC_FENCE_AFTER()   asm volatile("tcgen05.fence::after_thread_sync;" ::: "memory")
#define TC_FENCE_BEFORE()  asm volatile("tcgen05.fence::before_thread_sync;" ::: "memory")
#define TC_WAIT_LD()       asm volatile("tcgen05.wait::ld.sync.aligned;" ::: "memory")
#define FENCE_ASYNC()      asm volatile("fence.proxy.async.shared::cta;" ::: "memory")

#define TC_LD_32X32B_X32(r, ta) \
    asm volatile( \
        "tcgen05.ld.sync.aligned.32x32b.x32.b32 " \
        "{%0, %1, %2, %3, %4, %5, %6, %7, " \
        " %8, %9, %10, %11, %12, %13, %14, %15, " \
        " %16, %17, %18, %19, %20, %21, %22, %23, " \
        " %24, %25, %26, %27, %28, %29, %30, %31}, [%32];" \
        : "=r"((r)[0]),  "=r"((r)[1]),  "=r"((r)[2]),  "=r"((r)[3]), \
          "=r"((r)[4]),  "=r"((r)[5]),  "=r"((r)[6]),  "=r"((r)[7]), \
          "=r"((r)[8]),  "=r"((r)[9]),  "=r"((r)[10]), "=r"((r)[11]), \
          "=r"((r)[12]), "=r"((r)[13]), "=r"((r)[14]), "=r"((r)[15]), \
          "=r"((r)[16]), "=r"((r)[17]), "=r"((r)[18]), "=r"((r)[19]), \
          "=r"((r)[20]), "=r"((r)[21]), "=r"((r)[22]), "=r"((r)[23]), \
          "=r"((r)[24]), "=r"((r)[25]), "=r"((r)[26]), "=r"((r)[27]), \
          "=r"((r)[28]), "=r"((r)[29]), "=r"((r)[30]), "=r"((r)[31]) \
        : "r"(ta))

__device__ __forceinline__ void mma_bf16(u32 dt, u64 ad, u64 bd, u32 idesc, bool acc) {
    u32 en = acc ? 1u : 0u;
    asm volatile("{\n .reg .pred p;\n setp.ne.u32 p, %4, 0;\n"
        " tcgen05.mma.cta_group::1.kind::f16 [%0], %1, %2, %3, {%5,%5,%5,%5}, p;\n}"
        :: "r"(dt), "l"(ad), "l"(bd), "r"(idesc), "r"(en), "r"(0u) : "memory");
}
#endif  // TC_EN

static constexpr u32 IDESC_BF16 =
    (1u << 4) | (1u << 7) | (1u << 10) | ((128u / 8u) << 17) | ((128u / 16u) << 24);
static constexpr u32 IDESC_BF16_N64 =
    (1u << 4) | (1u << 7) | (1u << 10) | ((64u / 8u) << 17) | ((128u / 16u) << 24);
static constexpr u64 DESC_BASE =
    (2ull << 61) | (1ull << 46) | (64ull << 32) | (1ull << 16);
__device__ __forceinline__ u64 mk_desc(u32 addr) {
    return DESC_BASE | ((u64)(addr >> 4) & 0x3FFF);
}

// Scratch (allocation-free rule: device globals). Everything split-bf16.
__device__ __nv_bfloat16 g_Xh[(size_t)T_*D_],  g_Xl[(size_t)T_*D_];
__device__ __nv_bfloat16 g_Wqh[(size_t)D_*D_], g_Wql[(size_t)D_*D_];
__device__ __nv_bfloat16 g_Wkh[(size_t)D_*D_], g_Wkl[(size_t)D_*D_];
__device__ __nv_bfloat16 g_Wvh[(size_t)D_*D_], g_Wvl[(size_t)D_*D_];
__device__ __nv_bfloat16 g_Woh[(size_t)D_*D_], g_Wol[(size_t)D_*D_];
__device__ __nv_bfloat16 g_Qh[(size_t)NB_*H_*S_*DH_], g_Ql[(size_t)NB_*H_*S_*DH_];
__device__ __nv_bfloat16 g_Kh[(size_t)NB_*H_*S_*DH_], g_Kl[(size_t)NB_*H_*S_*DH_];
__device__ __nv_bfloat16 g_Vh[(size_t)NB_*H_*S_*DH_], g_Vl[(size_t)NB_*H_*S_*DH_];
__device__ __nv_bfloat16 g_ATh[(size_t)T_*D_], g_ATl[(size_t)T_*D_];

// ---------------------------------------------------------------------------
// Merged split pass: x + 4 weights in one launch.
// ---------------------------------------------------------------------------
__global__ __launch_bounds__(256, 4)
void split_all(const float* __restrict__ x,
               const float* __restrict__ wq, const float* __restrict__ wk,
               const float* __restrict__ wv, const float* __restrict__ wo) {
    const int NX8 = (T_ * D_) / 8;
    const int NW8 = (D_ * D_) / 8;        // 2^19
    const int i = blockIdx.x * 256 + threadIdx.x;
    const float* src;
    __nv_bfloat16 *hi, *lo;
    size_t e;
    if (i < NX8) {
        src = x; hi = g_Xh; lo = g_Xl; e = (size_t)i * 8;
    } else {
        const int j = i - NX8;
        const int sel = j >> 19;
        const int off = j & (NW8 - 1);
        src = (sel == 0) ? wq : (sel == 1) ? wk : (sel == 2) ? wv : wo;
        hi  = (sel == 0) ? g_Wqh : (sel == 1) ? g_Wkh : (sel == 2) ? g_Wvh : g_Woh;
        lo  = (sel == 0) ? g_Wql : (sel == 1) ? g_Wkl : (sel == 2) ? g_Wvl : g_Wol;
        e = (size_t)off * 8;
    }
    uint4 h, l;
    split8(*(const float4*)(src + e), *(const float4*)(src + e + 4), h, l);
    *(uint4*)(hi + e) = h;
    *(uint4*)(lo + e) = l;
}

// ---------------------------------------------------------------------------
// GEMM core v3: 256x128 CTA tile, BK=64, SW128, SINGLE 96KB stage, designed
// for 2 CTAs/SM: one CTA's STS/sync/LDG overlaps the other CTA's MMA.
// No register prefetch (keeps regs < 128 for occupancy 2).
// Stage layout (16KB plane tiles): [A0h A0l A1h A1l Wh Wl].
// TMEM: 256 cols (2 quadrants of 128x128).
// ---------------------------------------------------------------------------
#if TC_EN
__device__ __forceinline__ u32 gemm_core(
    char* smem, u32 sb,
    const __nv_bfloat16* __restrict__ Ah, const __nv_bfloat16* __restrict__ Al,
    const __nv_bfloat16* __restrict__ Wh, const __nv_bfloat16* __restrict__ Wl,
    int m0, int n0, int tid, int wid) {
    const u32 mbar = sb + 98304;
    const u32 tmemp = sb + 98312;

    if (wid == 0) { TC_ALLOC(tmemp, 256); TC_RELQ(); }
    if (tid == 0) { MBAR_INIT(mbar, 1); }
    __syncthreads();
    u32 tmem;
    asm volatile("ld.shared.b32 %0, [%1];" : "=r"(tmem) : "r"(tmemp));

    const int c8 = tid & 7;
    const int r0 = tid >> 3;   // 0..31
    const size_t a0 = (size_t)(m0 + r0) * D_ + c8 * 8;
    const size_t a1 = (size_t)(m0 + 128 + r0) * D_ + c8 * 8;
    const size_t w0 = (size_t)(n0 + r0) * D_ + c8 * 8;
    const u32 soff = swz((u32)(r0 * 128 + c8 * 16));

    int ph = 0;
    const int NKT = D_ / 64;   // 32
    for (int kt = 0; kt < NKT; ++kt) {
        if (kt > 0) { MBAR_WAIT(mbar, ph); ph ^= 1; }  // MMA(kt-1) done
        const int kk = kt * 64;
#pragma unroll
        for (int i = 0; i < 4; ++i) {
            const size_t r = (size_t)(32 * i) * D_ + kk;
            const u32 off = soff + (u32)(i * 4096);
            *(uint4*)(smem + off)         = *(const uint4*)(Ah + a0 + r);
            *(uint4*)(smem + 16384 + off) = *(const uint4*)(Al + a0 + r);
            *(uint4*)(smem + 32768 + off) = *(const uint4*)(Ah + a1 + r);
            *(uint4*)(smem + 49152 + off) = *(const uint4*)(Al + a1 + r);
            *(uint4*)(smem + 65536 + off) = *(const uint4*)(Wh + w0 + r);
            *(uint4*)(smem + 81920 + off) = *(const uint4*)(Wl + w0 + r);
        }
        FENCE_ASYNC();
        __syncthreads();
        if (wid == 0 && elect1()) {
#pragma unroll
            for (int mt = 0; mt < 2; ++mt) {
                const u32 dst = tmem + mt * 128;
                const u32 ab = sb + mt * 32768u;
                const u32 wb = sb + 65536u;
#pragma unroll
                for (int t = 0; t < 3; ++t) {
                    u64 ad = mk_desc(ab + ((t == 2) ? 16384u : 0u));
                    u64 bd = mk_desc(wb + ((t == 1) ? 16384u : 0u));
#pragma unroll
                    for (int k = 0; k < 4; ++k)
                        mma_bf16(dst, ad + k * 2, bd + k * 2, IDESC_BF16,
                                 (kt > 0) || (t > 0) || (k > 0));
                }
            }
            TC_COMMIT(mbar);
        }
    }
    MBAR_WAIT(mbar, ph);
    TC_FENCE_AFTER();
    return tmem;
}
#endif

// ---------------------------------------------------------------------------
// Fused QKV projection: grid (48, 32). blockIdx.x>>4 selects weight/output,
// n0 = (blockIdx.x&15)*128.
// ---------------------------------------------------------------------------
__global__ __launch_bounds__(256, 2)
void tc_gemm_qkv(const __nv_bfloat16* __restrict__ Ah, const __nv_bfloat16* __restrict__ Al,
                 const __nv_bfloat16* __restrict__ Wqh, const __nv_bfloat16* __restrict__ Wql,
                 const __nv_bfloat16* __restrict__ Wkh, const __nv_bfloat16* __restrict__ Wkl,
                 const __nv_bfloat16* __restrict__ Wvh, const __nv_bfloat16* __restrict__ Wvl,
                 const int* __restrict__ pos) {
    const int tid = threadIdx.x;
    const int wid = tid >> 5;
    const int lane = tid & 31;
    const int wsel = blockIdx.x >> 4;              // 0=Q 1=K 2=V
    const int n0 = (blockIdx.x & 15) * 128;
    const int m0 = blockIdx.y * 256;
    const int mrow = 32 * (wid & 3) + lane;
    const int tcol = (wid < 4) ? 0 : 64;

    const __nv_bfloat16* Wh = (wsel == 0) ? Wqh : (wsel == 1) ? Wkh : Wvh;
    const __nv_bfloat16* Wl = (wsel == 0) ? Wql : (wsel == 1) ? Wkl : Wvl;
    __nv_bfloat16* Ph = (wsel == 0) ? g_Qh : (wsel == 1) ? g_Kh : g_Vh;
    __nv_bfloat16* Pl = (wsel == 0) ? g_Ql : (wsel == 1) ? g_Kl : g_Vl;

    u32 d[64];

#if TC_EN
    extern __shared__ __align__(1024) char smem[];
    const u32 sb = smem_u32(smem);
    const u32 tmem = gemm_core(smem, sb, Ah, Al, Wh, Wl, m0, n0, tid, wid);
#endif

#pragma unroll
    for (int mt = 0; mt < 2; ++mt) {
        const int m = m0 + mt * 128 + mrow;
#if TC_EN
        TC_LD_32X32B_X32(d,      tmem + mt * 128 + tcol);
        TC_LD_32X32B_X32(d + 32, tmem + mt * 128 + tcol + 32);
        TC_WAIT_LD();
#else
        for (int c = 0; c < 64; ++c) {
            float s = 0.f;
            for (int k = 0; k < D_; ++k) {
                float a = __bfloat162float(Ah[(size_t)m * D_ + k]) +
                          __bfloat162float(Al[(size_t)m * D_ + k]);
                float w = __bfloat162float(Wh[(size_t)(n0 + tcol + c) * D_ + k]) +
                          __bfloat162float(Wl[(size_t)(n0 + tcol + c) * D_ + k]);
                s += a * w;
            }
            d[c] = __float_as_uint(s);
        }
#endif
        const int b = m >> 11;
        const int s = m & (S_ - 1);
        const int bh = b * H_ + (n0 >> 7);
        if (wsel != 2) {  // Q/K: RoPE + planes [bh][s][dh]
            const float fp = (float)pos[s];
#pragma unroll 8
            for (int g = 0; g < 32; ++g) {
                const int j = 2 * g;
                const int jj = tcol + j;
                const float inv = expf(-(float)jj * (9.210340371976184f / 128.0f));
                float sn, cs;
                sincosf(fp * inv, &sn, &cs);
                const float x1 = __uint_as_float(d[j]);
                const float x2 = __uint_as_float(d[j + 1]);
                d[j]     = __float_as_uint(x1 * cs - x2 * sn);
                d[j + 1] = __float_as_uint(x1 * sn + x2 * cs);
            }
            const size_t eb = ((size_t)bh * S_ + s) * DH_ + tcol;
#pragma unroll
            for (int c = 0; c < 64; c += 8) {
                uint4 hi, lo;
                split8(make_float4(__uint_as_float(d[c]),     __uint_as_float(d[c + 1]),
                                   __uint_as_float(d[c + 2]), __uint_as_float(d[c + 3])),
                       make_float4(__uint_as_float(d[c + 4]), __uint_as_float(d[c + 5]),
                                   __uint_as_float(d[c + 6]), __uint_as_float(d[c + 7])),
                       hi, lo);
                *(uint4*)(Ph + eb + c) = hi;
                *(uint4*)(Pl + eb + c) = lo;
            }
        } else {          // V: planes [bh][dh][s]
            const size_t eb = (size_t)bh * DH_ * S_ + s;
#pragma unroll
            for (int j = 0; j < 64; ++j) {
                const int dh = tcol + j;
                float v = __uint_as_float(d[j]);
                __nv_bfloat16 hb = __float2bfloat16(v);
                Ph[eb + (size_t)dh * S_] = hb;
                Pl[eb + (size_t)dh * S_] = __float2bfloat16(v - __bfloat162float(hb));
            }
        }
    }
#if TC_EN
    __syncthreads();
    if (wid == 0) TC_DEALLOC(tmem, 256);
#endif
}

// ---------------------------------------------------------------------------
// Output GEMM: grid (16, 32), 256x128 tile, plain fp32 write.
// ---------------------------------------------------------------------------
__global__ __launch_bounds__(256, 2)
void tc_gemm_out(const __nv_bfloat16* __restrict__ Ah, const __nv_bfloat16* __restrict__ Al,
                 const __nv_bfloat16* __restrict__ Wh, const __nv_bfloat16* __restrict__ Wl,
                 float* __restrict__ Cf) {
    const int tid = threadIdx.x;
    const int wid = tid >> 5;
    const int lane = tid & 31;
    const int n0 = blockIdx.x * 128;
    const int m0 = blockIdx.y * 256;
    const int mrow = 32 * (wid & 3) + lane;
    const int tcol = (wid < 4) ? 0 : 64;

    u32 d[64];

#if TC_EN
    extern __shared__ __align__(1024) char smem[];
    const u32 sb = smem_u32(smem);
    const u32 tmem = gemm_core(smem, sb, Ah, Al, Wh, Wl, m0, n0, tid, wid);
#endif

#pragma unroll
    for (int mt = 0; mt < 2; ++mt) {
        const int m = m0 + mt * 128 + mrow;
#if TC_EN
        TC_LD_32X32B_X32(d,      tmem + mt * 128 + tcol);
        TC_LD_32X32B_X32(d + 32, tmem + mt * 128 + tcol + 32);
        TC_WAIT_LD();
#else
        for (int c = 0; c < 64; ++c) {
            float s = 0.f;
            for (int k = 0; k < D_; ++k) {
                float a = __bfloat162float(Ah[(size_t)m * D_ + k]) +
                          __bfloat162float(Al[(size_t)m * D_ + k]);
                float w = __bfloat162float(Wh[(size_t)(n0 + tcol + c) * D_ + k]) +
                          __bfloat162float(Wl[(size_t)(n0 + tcol + c) * D_ + k]);
                s += a * w;
            }
            d[c] = __float_as_uint(s);
        }
#endif
        float* dst = Cf + (size_t)m * D_ + n0 + tcol;
#pragma unroll
        for (int c = 0; c < 64; c += 4)
            *(float4*)(dst + c) = make_float4(
                __uint_as_float(d[c]), __uint_as_float(d[c + 1]),
                __uint_as_float(d[c + 2]), __uint_as_float(d[c + 3]));
    }
#if TC_EN
    __syncthreads();
    if (wid == 0) TC_DEALLOC(tmem, 256);
#endif
}

// ---------------------------------------------------------------------------
// Flash attention v3 (round-15 version, best measured).
// ---------------------------------------------------------------------------
__global__ __launch_bounds__(256, 1)
void flash_tc() {
    const int tid = threadIdx.x;
    const int bh = blockIdx.x;
    const int qt = 15 - blockIdx.y;
    const int q0 = qt * 128;
    const size_t base = (size_t)bh * S_ * DH_;
    const int b = bh >> 4;
    const int h = bh & 15;
    const float sc = 0.08838834764831845f;

#if TC_EN
    extern __shared__ __align__(1024) char fsm[];
    const u32 sb = smem_u32(fsm);
    const u32 QS = sb;
    const u32 KB = sb + 65536;
    const u32 VB = sb + 131072;
    const u32 PB = sb + 196608;
    const u32 MB_S0 = sb + 229376;
    const u32 MB_S1 = sb + 229384;
    const u32 MB_O  = sb + 229392;
    const u32 TMEMP = sb + 229400;
    float* slf = (float*)(fsm + 229408);

    const int wid = tid >> 5;
    const int lane = tid & 31;
    const int q_rel = 32 * (wid & 3) + lane;
    const int tcol_s = (wid < 4) ? 0 : 32;
    const int tcol_o = (wid < 4) ? 0 : 64;

    if (wid == 0) { TC_ALLOC(TMEMP, 256); TC_RELQ(); }
    if (tid == 0) { MBAR_INIT(MB_S0, 1); MBAR_INIT(MB_S1, 1); MBAR_INIT(MB_O, 1); }
    __syncthreads();
    u32 tmem;
    asm volatile("ld.shared.b32 %0, [%1];" : "=r"(tmem) : "r"(TMEMP));
    const u32 tO = tmem;
    const u32 tS0 = tmem + 128, tS1 = tmem + 192;

    const int c8 = tid & 7;
    const int r0 = (tid >> 3) & 31;
    const u32 soff = swz((u32)(r0 * 128 + c8 * 16));
    const int nst = 2 * (qt + 1);

#pragma unroll
    for (int pl = 0; pl < 2; ++pl) {
        const __nv_bfloat16* qp = pl ? g_Ql : g_Qh;
#pragma unroll
        for (int kb = 0; kb < 2; ++kb)
#pragma unroll
            for (int i = 0; i < 4; ++i) {
                uint4 v = *(const uint4*)(qp + base +
                    (size_t)(q0 + r0 + 32 * i) * DH_ + kb * 64 + c8 * 8);
                *(uint4*)(fsm + pl * 32768 + kb * 16384 + i * 4096 + soff) = v;
            }
    }
#pragma unroll
    for (int jb = 0; jb < 2; ++jb) {
        if (jb < nst) {
            const int jj0 = jb * 64;
#pragma unroll
            for (int pl = 0; pl < 2; ++pl) {
                const __nv_bfloat16* kp = pl ? g_Kl : g_Kh;
#pragma unroll
                for (int kb = 0; kb < 2; ++kb)
#pragma unroll
                    for (int i = 0; i < 2; ++i) {
                        uint4 v = *(const uint4*)(kp + base +
                            (size_t)(jj0 + r0 + 32 * i) * DH_ + kb * 64 + c8 * 8);
                        *(uint4*)(fsm + 65536 + jb * 32768 + pl * 16384 +
                                  kb * 8192 + i * 4096 + soff) = v;
                    }
            }
        }
    }
    {
#pragma unroll
        for (int pl = 0; pl < 2; ++pl) {
            const __nv_bfloat16* vp = pl ? g_Vl : g_Vh;
#pragma unroll
            for (int i = 0; i < 4; ++i) {
                uint4 v = *(const uint4*)(vp + base +
                    (size_t)(r0 + 32 * i) * S_ + 0 + c8 * 8);
                *(uint4*)(fsm + 131072 + pl * 16384 + i * 4096 + soff) = v;
            }
        }
    }
    FENCE_ASYNC();
    __syncthreads();

    if (wid == 0 && elect1()) {
        TC_FENCE_AFTER();
        int first = 1;
#pragma unroll
        for (int t = 0; t < 3; ++t) {
            const int pa = (t == 2) ? 1 : 0;
            const int pb = (t == 1) ? 1 : 0;
#pragma unroll
            for (int kb = 0; kb < 2; ++kb) {
                u64 qd = mk_desc(QS + pa * 32768 + kb * 16384);
                u64 kd = mk_desc(KB + pb * 16384 + kb * 8192);
#pragma unroll
                for (int k = 0; k < 4; ++k) {
                    mma_bf16(tS0, qd + k * 2, kd + k * 2, IDESC_BF16_N64, !first);
                    first = 0;
                }
            }
        }
        TC_COMMIT(MB_S0);
    }

    int ph_s0 = 0, ph_s1 = 0, ph_o = 0;
    float l_part = 0.f;

    for (int j = 0; j < nst; ++j) {
        const int buf = j & 1;
        const int nbuf = buf ^ 1;
        const u32 tSc = buf ? tS1 : tS0;
        const u32 tSn = buf ? tS0 : tS1;

        if (j + 1 < nst && wid == 0 && elect1()) {
            int first = 1;
#pragma unroll
            for (int t = 0; t < 3; ++t) {
                const int pa = (t == 2) ? 1 : 0;
                const int pb = (t == 1) ? 1 : 0;
#pragma unroll
                for (int kb = 0; kb < 2; ++kb) {
                    u64 qd = mk_desc(QS + pa * 32768 + kb * 16384);
                    u64 kd = mk_desc(KB + nbuf * 32768 + pb * 16384 + kb * 8192);
#pragma unroll
                    for (int k = 0; k < 4; ++k) {
                        mma_bf16(tSn, qd + k * 2, kd + k * 2, IDESC_BF16_N64, !first);
                        first = 0;
                    }
                }
            }
            TC_COMMIT(nbuf ? MB_S1 : MB_S0);
        }

        uint4 pK[8], pV[8];
        if (j + 2 < nst) {
            const int jj0 = (j + 2) * 64;
            int ix = 0;
#pragma unroll
            for (int pl = 0; pl < 2; ++pl) {
                const __nv_bfloat16* kp = pl ? g_Kl : g_Kh;
#pragma unroll
                for (int kb = 0; kb < 2; ++kb)
#pragma unroll
                    for (int i = 0; i < 2; ++i)
                        pK[ix++] = *(const uint4*)(kp + base +
                            (size_t)(jj0 + r0 + 32 * i) * DH_ + kb * 64 + c8 * 8);
            }
        }
        if (j + 1 < nst) {
            const int jv0 = (j + 1) * 64;
            int ix = 0;
#pragma unroll
            for (int pl = 0; pl < 2; ++pl) {
                const __nv_bfloat16* vp = pl ? g_Vl : g_Vh;
#pragma unroll
                for (int i = 0; i < 4; ++i)
                    pV[ix++] = *(const uint4*)(vp + base +
                        (size_t)(r0 + 32 * i) * S_ + jv0 + c8 * 8);
            }
        }

        if (j > 0) { MBAR_WAIT(MB_O, ph_o); ph_o ^= 1; }
        if (buf == 0) { MBAR_WAIT(MB_S0, ph_s0); ph_s0 ^= 1; }
        else          { MBAR_WAIT(MB_S1, ph_s1); ph_s1 ^= 1; }
        TC_FENCE_AFTER();

        float p[32];
        TC_LD_32X32B_X32((u32*)p, tSc + tcol_s);
        TC_WAIT_LD();
        TC_FENCE_BEFORE();
        const int thr = q0 + q_rel - 64 * j - tcol_s;
        float lsum = 0.f;
#pragma unroll
        for (int c = 0; c < 32; ++c) {
            float s = __uint_as_float(((u32*)p)[c]);
            float v = (c > thr) ? 0.f : __expf(s * sc);
            p[c] = v; lsum += v;
        }
        l_part += lsum;

#pragma unroll
        for (int c4p = 0; c4p < 4; ++c4p) {
            uint4 hi, lo;
            split8(make_float4(p[c4p*8], p[c4p*8+1], p[c4p*8+2], p[c4p*8+3]),
                   make_float4(p[c4p*8+4], p[c4p*8+5], p[c4p*8+6], p[c4p*8+7]),
                   hi, lo);
            const u32 poff = swz((u32)(q_rel * 128 + tcol_s * 2 + c4p * 16));
            *(uint4*)(fsm + 196608 + poff)         = hi;
            *(uint4*)(fsm + 196608 + 16384 + poff) = lo;
        }
        FENCE_ASYNC();
        __syncthreads();

        if (wid == 0 && elect1()) {
            TC_FENCE_AFTER();
#pragma unroll
            for (int t = 0; t < 3; ++t) {
                const int pa = (t == 2) ? 1 : 0;
                const int pb = (t == 1) ? 1 : 0;
                u64 pd = mk_desc(PB + pa * 16384);
                u64 vd = mk_desc(VB + buf * 32768 + pb * 16384);
#pragma unroll
                for (int k = 0; k < 4; ++k)
                    mma_bf16(tO, pd + k * 2, vd + k * 2, IDESC_BF16,
                             (j > 0) || (t > 0) || (k > 0));
            }
            TC_COMMIT(MB_O);
        }

        if (j + 2 < nst) {
            int ix = 0;
#pragma unroll
            for (int pl = 0; pl < 2; ++pl)
#pragma unroll
                for (int kb = 0; kb < 2; ++kb)
#pragma unroll
                    for (int i = 0; i < 2; ++i)
                        *(uint4*)(fsm + 65536 + buf * 32768 + pl * 16384 +
                                  kb * 8192 + i * 4096 + soff) = pK[ix++];
        }
        if (j + 1 < nst) {
            int ix = 0;
#pragma unroll
            for (int pl = 0; pl < 2; ++pl)
#pragma unroll
                for (int i = 0; i < 4; ++i)
                    *(uint4*)(fsm + 131072 + nbuf * 32768 + pl * 16384 +
                              i * 4096 + soff) = pV[ix++];
        }
        FENCE_ASYNC();
        __syncthreads();
    }

    MBAR_WAIT(MB_O, ph_o);
    TC_FENCE_AFTER();

    slf[(wid < 4 ? 0 : 128) + q_rel] = l_part;
    __syncthreads();
    const float invl = 1.0f / (slf[q_rel] + slf[128 + q_rel]);

    float o[64];
    TC_LD_32X32B_X32((u32*)o,      tO + tcol_o);
    TC_LD_32X32B_X32((u32*)o + 32, tO + tcol_o + 32);
    TC_WAIT_LD();
    TC_FENCE_BEFORE();
    __syncthreads();
    if (wid == 0) TC_DEALLOC(tmem, 256);

    const size_t eb = (size_t)(b * S_ + q0 + q_rel) * D_ + h * DH_ + tcol_o;
#pragma unroll
    for (int g8 = 0; g8 < 8; ++g8) {
        float f[8];
#pragma unroll
        for (int j = 0; j < 8; ++j) f[j] = o[g8 * 8 + j] * invl;
        uint4 hi, lo;
        split8(make_float4(f[0], f[1], f[2], f[3]),
               make_float4(f[4], f[5], f[6], f[7]), hi, lo);
        *(uint4*)(g_ATh + eb + g8 * 8) = hi;
        *(uint4*)(g_ATl + eb + g8 * 8) = lo;
    }
#else
    if (tid < 128) {
        const int q = q0 + tid;
        float O[128];
        for (int d0 = 0; d0 < 128; ++d0) O[d0] = 0.f;
        float l = 0.f;
        for (int c = 0; c <= q; ++c) {
            float s = 0.f;
            for (int d0 = 0; d0 < 128; ++d0) {
                float qv = __bfloat162float(g_Qh[base + (size_t)q * DH_ + d0]) +
                           __bfloat162float(g_Ql[base + (size_t)q * DH_ + d0]);
                float kv = __bfloat162float(g_Kh[base + (size_t)c * DH_ + d0]) +
                           __bfloat162float(g_Kl[base + (size_t)c * DH_ + d0]);
                s += qv * kv;
            }
            float v = __expf(s * sc);
            l += v;
            for (int d0 = 0; d0 < 128; ++d0) {
                float vv = __bfloat162float(g_Vh[base + (size_t)d0 * S_ + c]) +
                           __bfloat162float(g_Vl[base + (size_t)d0 * S_ + c]);
                O[d0] += v * vv;
            }
        }
        const size_t eb = (size_t)(b * S_ + q) * D_ + h * DH_;
        for (int d0 = 0; d0 < 128; ++d0) {
            float v = O[d0] / l;
            __nv_bfloat16 hb = __float2bfloat16(v);
            g_ATh[eb + d0] = hb;
            g_ATl[eb + d0] = __float2bfloat16(v - __bfloat162float(hb));
        }
    }
#endif
}

// ---------------------------------------------------------------------------
extern "C" void kernel_launch(void* const* d_in, const int* in_sizes, int n_in,
                              void* d_out, int out_size) {
    const float* x  = (const float*)d_in[0];
    const int*   tp = (const int*)d_in[1];
    const float* wq = (const float*)d_in[2];
    const float* wk = (const float*)d_in[3];
    const float* wv = (const float*)d_in[4];
    const float* wo = (const float*)d_in[5];
    float* out = (float*)d_out;

    __nv_bfloat16 *Xh, *Xl, *Wqh, *Wql, *Wkh, *Wkl, *Wvh, *Wvl, *Woh, *Wol;
    __nv_bfloat16 *ATh, *ATl;
    cudaGetSymbolAddress((void**)&Xh,  g_Xh);  cudaGetSymbolAddress((void**)&Xl,  g_Xl);
    cudaGetSymbolAddress((void**)&Wqh, g_Wqh); cudaGetSymbolAddress((void**)&Wql, g_Wql);
    cudaGetSymbolAddress((void**)&Wkh, g_Wkh); cudaGetSymbolAddress((void**)&Wkl, g_Wkl);
    cudaGetSymbolAddress((void**)&Wvh, g_Wvh); cudaGetSymbolAddress((void**)&Wvl, g_Wvl);
    cudaGetSymbolAddress((void**)&Woh, g_Woh); cudaGetSymbolAddress((void**)&Wol, g_Wol);
    cudaGetSymbolAddress((void**)&ATh, g_ATh); cudaGetSymbolAddress((void**)&ATl, g_ATl);

    const int smem_gemm = 98304 + 64;   // 96KB stage + ctrl (2 CTAs/SM)
    cudaFuncSetAttribute(tc_gemm_qkv, cudaFuncAttributeMaxDynamicSharedMemorySize, smem_gemm);
    cudaFuncSetAttribute(tc_gemm_out, cudaFuncAttributeMaxDynamicSharedMemorySize, smem_gemm);

    const int smem_flash = 229376 + 32 + 1024;
    cudaFuncSetAttribute(flash_tc,
                         cudaFuncAttributeMaxDynamicSharedMemorySize, smem_flash);

    const int ntot = (T_ * D_) / 8 + 4 * ((D_ * D_) / 8);
    split_all<<<ntot / 256, 256>>>(x, wq, wk, wv, wo);

    tc_gemm_qkv<<<dim3(48, T_ / 256), 256, smem_gemm>>>(
        Xh, Xl, Wqh, Wql, Wkh, Wkl, Wvh, Wvl, tp);

    flash_tc<<<dim3(NB_ * H_, S_ / 128), 256, smem_flash>>>();

    tc_gemm_out<<<dim3(D_ / 128, T_ / 256), 256, smem_gemm>>>(
        ATh, ATl, Woh, Wol, out);
}

// round 17
// speedup vs baseline: 1.1440x; 1.1440x over previous
#include <cuda_runtime.h>
#include <cuda_bf16.h>
#include <math.h>
#include <cstdint>

#define NB_ 4
#define S_ 2048
#define D_ 2048
#define H_ 16
#define DH_ 128
#define T_ (NB_*S_)

typedef unsigned long long u64;
typedef unsigned int u32;

#if !defined(__CUDA_ARCH__) || defined(__CUDA_ARCH_FEAT_SM103_ALL)
#define TC_EN 1
#else
#define TC_EN 0
#endif

// ---------------- generic helpers ----------------
__device__ __forceinline__ u32 smem_u32(const void* p) {
    u32 a;
    asm("{ .reg .u64 t; cvta.to.shared.u64 t, %1; cvt.u32.u64 %0, t; }"
        : "=r"(a) : "l"(p));
    return a;
}
__device__ __forceinline__ u32 elect1() {
    u32 p;
    asm volatile("{ .reg .pred p; elect.sync _|p, 0xFFFFFFFF; selp.b32 %0,1,0,p; }"
                 : "=r"(p));
    return p;
}
__device__ __forceinline__ u32 swz(u32 x) { return x ^ ((x >> 3) & 0x70); }
__device__ __forceinline__ u32 packbf(float x, float y) {
    u32 r; asm("cvt.rn.bf16x2.f32 %0, %1, %2;" : "=r"(r) : "f"(y), "f"(x));
    return r;
}
__device__ __forceinline__ void split8(float4 v0, float4 v1, uint4 &hi, uint4 &lo) {
    float f[8] = {v0.x, v0.y, v0.z, v0.w, v1.x, v1.y, v1.z, v1.w};
    u32 hw[4], lw[4];
#pragma unroll
    for (int j = 0; j < 4; ++j) {
        float a = f[2 * j], b = f[2 * j + 1];
        float ah = __bfloat162float(__float2bfloat16(a));
        float bh = __bfloat162float(__float2bfloat16(b));
        hw[j] = packbf(ah, bh);
        lw[j] = packbf(a - ah, b - bh);
    }
    hi = make_uint4(hw[0], hw[1], hw[2], hw[3]);
    lo = make_uint4(lw[0], lw[1], lw[2], lw[3]);
}

#define MBAR_INIT(a, c) \
    asm volatile("mbarrier.init.shared.b64 [%0], %1;" :: "r"(a), "r"(c) : "memory")

#define MBAR_WAIT(a, ph) do { \
    u32 _m = (a), _p = (ph), _d; \
    asm volatile("{\n .reg .pred p;\n" \
        " mbarrier.try_wait.parity.acquire.cta.shared::cta.b64 p, [%1], %2;\n" \
        " selp.b32 %0,1,0,p;\n}" : "=r"(_d) : "r"(_m), "r"(_p) : "memory"); \
    if (!_d) { \
        asm volatile("{\n .reg .pred P;\n" \
            "LW%=:\n mbarrier.try_wait.parity.acquire.cta.shared::cta.b64 P, [%0], %1, 0x989680;\n" \
            " @P bra.uni LD%=;\n bra.uni LW%=;\nLD%=:\n}" \
            :: "r"(_m), "r"(_p) : "memory"); \
    } \
} while (0)

#if TC_EN
#define TC_ALLOC(sa, n) \
    asm volatile("tcgen05.alloc.cta_group::1.sync.aligned.shared::cta.b32 [%0], %1;" \
                 :: "r"(sa), "r"(n) : "memory")
#define TC_RELQ() \
    asm volatile("tcgen05.relinquish_alloc_permit.cta_group::1.sync.aligned;")
#define TC_DEALLOC(t, n) \
    asm volatile("tcgen05.dealloc.cta_group::1.sync.aligned.b32 %0, %1;" :: "r"(t), "r"(n))
#define TC_COMMIT(mb) \
    asm volatile("tcgen05.commit.cta_group::1.mbarrier::arrive::one.shared::cluster.b64 [%0];" \
                 :: "r"(mb) : "memory")
#define TC_FENCE_AFTER()   asm volatile("tcgen05.fence::after_thread_sync;" ::: "memory")
#define TC_FENCE_BEFORE()  asm volatile("tcgen05.fence::before_thread_sync;" ::: "memory")
#define TC_WAIT_LD()       asm volatile("tcgen05.wait::ld.sync.aligned;" ::: "memory")
#define FENCE_ASYNC()      asm volatile("fence.proxy.async.shared::cta;" ::: "memory")

#define TC_LD_32X32B_X32(r, ta) \
    asm volatile( \
        "tcgen05.ld.sync.aligned.32x32b.x32.b32 " \
        "{%0, %1, %2, %3, %4, %5, %6, %7, " \
        " %8, %9, %10, %11, %12, %13, %14, %15, " \
        " %16, %17, %18, %19, %20, %21, %22, %23, " \
        " %24, %25, %26, %27, %28, %29, %30, %31}, [%32];" \
        : "=r"((r)[0]),  "=r"((r)[1]),  "=r"((r)[2]),  "=r"((r)[3]), \
          "=r"((r)[4]),  "=r"((r)[5]),  "=r"((r)[6]),  "=r"((r)[7]), \
          "=r"((r)[8]),  "=r"((r)[9]),  "=r"((r)[10]), "=r"((r)[11]), \
          "=r"((r)[12]), "=r"((r)[13]), "=r"((r)[14]), "=r"((r)[15]), \
          "=r"((r)[16]), "=r"((r)[17]), "=r"((r)[18]), "=r"((r)[19]), \
          "=r"((r)[20]), "=r"((r)[21]), "=r"((r)[22]), "=r"((r)[23]), \
          "=r"((r)[24]), "=r"((r)[25]), "=r"((r)[26]), "=r"((r)[27]), \
          "=r"((r)[28]), "=r"((r)[29]), "=r"((r)[30]), "=r"((r)[31]) \
        : "r"(ta))

__device__ __forceinline__ void mma_bf16(u32 dt, u64 ad, u64 bd, u32 idesc, bool acc) {
    u32 en = acc ? 1u : 0u;
    asm volatile("{\n .reg .pred p;\n setp.ne.u32 p, %4, 0;\n"
        " tcgen05.mma.cta_group::1.kind::f16 [%0], %1, %2, %3, {%5,%5,%5,%5}, p;\n}"
        :: "r"(dt), "l"(ad), "l"(bd), "r"(idesc), "r"(en), "r"(0u) : "memory");
}
#endif  // TC_EN

static constexpr u32 IDESC_BF16 =
    (1u << 4) | (1u << 7) | (1u << 10) | ((128u / 8u) << 17) | ((128u / 16u) << 24);
static constexpr u32 IDESC_BF16_N64 =
    (1u << 4) | (1u << 7) | (1u << 10) | ((64u / 8u) << 17) | ((128u / 16u) << 24);
static constexpr u64 DESC_BASE =
    (2ull << 61) | (1ull << 46) | (64ull << 32) | (1ull << 16);
__device__ __forceinline__ u64 mk_desc(u32 addr) {
    return DESC_BASE | ((u64)(addr >> 4) & 0x3FFF);
}

// Scratch (allocation-free rule: device globals). Everything split-bf16.
__device__ __nv_bfloat16 g_Xh[(size_t)T_*D_],  g_Xl[(size_t)T_*D_];
__device__ __nv_bfloat16 g_Wqh[(size_t)D_*D_], g_Wql[(size_t)D_*D_];
__device__ __nv_bfloat16 g_Wkh[(size_t)D_*D_], g_Wkl[(size_t)D_*D_];
__device__ __nv_bfloat16 g_Wvh[(size_t)D_*D_], g_Wvl[(size_t)D_*D_];
__device__ __nv_bfloat16 g_Woh[(size_t)D_*D_], g_Wol[(size_t)D_*D_];
__device__ __nv_bfloat16 g_Qh[(size_t)NB_*H_*S_*DH_], g_Ql[(size_t)NB_*H_*S_*DH_];
__device__ __nv_bfloat16 g_Kh[(size_t)NB_*H_*S_*DH_], g_Kl[(size_t)NB_*H_*S_*DH_];
__device__ __nv_bfloat16 g_Vh[(size_t)NB_*H_*S_*DH_], g_Vl[(size_t)NB_*H_*S_*DH_];
__device__ __nv_bfloat16 g_ATh[(size_t)T_*D_], g_ATl[(size_t)T_*D_];

// ---------------------------------------------------------------------------
// Merged split pass: x + 4 weights in one launch.
// ---------------------------------------------------------------------------
__global__ __launch_bounds__(256, 4)
void split_all(const float* __restrict__ x,
               const float* __restrict__ wq, const float* __restrict__ wk,
               const float* __restrict__ wv, const float* __restrict__ wo) {
    const int NX8 = (T_ * D_) / 8;
    const int NW8 = (D_ * D_) / 8;        // 2^19
    const int i = blockIdx.x * 256 + threadIdx.x;
    const float* src;
    __nv_bfloat16 *hi, *lo;
    size_t e;
    if (i < NX8) {
        src = x; hi = g_Xh; lo = g_Xl; e = (size_t)i * 8;
    } else {
        const int j = i - NX8;
        const int sel = j >> 19;
        const int off = j & (NW8 - 1);
        src = (sel == 0) ? wq : (sel == 1) ? wk : (sel == 2) ? wv : wo;
        hi  = (sel == 0) ? g_Wqh : (sel == 1) ? g_Wkh : (sel == 2) ? g_Wvh : g_Woh;
        lo  = (sel == 0) ? g_Wql : (sel == 1) ? g_Wkl : (sel == 2) ? g_Wvl : g_Wol;
        e = (size_t)off * 8;
    }
    uint4 h, l;
    split8(*(const float4*)(src + e), *(const float4*)(src + e + 4), h, l);
    *(uint4*)(hi + e) = h;
    *(uint4*)(lo + e) = l;
}

// ---------------------------------------------------------------------------
// GEMM core (ROUND-13 version, best measured): 256x256 CTA tile, BK=64,
// SW128 single 128KB buffer, full register prefetch of the next K-tile.
// ---------------------------------------------------------------------------
#if TC_EN
__device__ __forceinline__ u32 gemm_core(
    char* smem, u32 sb,
    const __nv_bfloat16* __restrict__ Ah, const __nv_bfloat16* __restrict__ Al,
    const __nv_bfloat16* __restrict__ Wh, const __nv_bfloat16* __restrict__ Wl,
    int m0, int n0, int tid, int wid) {
    const u32 mbar = sb + 131072;
    const u32 tmemp = sb + 131080;

    if (wid == 0) { TC_ALLOC(tmemp, 512); TC_RELQ(); }
    if (tid == 0) { MBAR_INIT(mbar, 1); }
    __syncthreads();
    u32 tmem;
    asm volatile("ld.shared.b32 %0, [%1];" : "=r"(tmem) : "r"(tmemp));

    const int c8 = tid & 7;
    const int r0 = tid >> 3;
    const size_t a0off = (size_t)(m0 + r0) * D_ + c8 * 8;
    const size_t a1off = (size_t)(m0 + 128 + r0) * D_ + c8 * 8;
    const size_t w0off = (size_t)(n0 + r0) * D_ + c8 * 8;
    const size_t w1off = (size_t)(n0 + 128 + r0) * D_ + c8 * 8;
    const u32 soff = swz((u32)(r0 * 128 + c8 * 16));

    uint4 pA[16], pW[16];
#pragma unroll
    for (int i = 0; i < 4; ++i) {
        const size_t r = (size_t)(32 * i) * D_;
        pA[i]      = *(const uint4*)(Ah + a0off + r);
        pA[4 + i]  = *(const uint4*)(Al + a0off + r);
        pA[8 + i]  = *(const uint4*)(Ah + a1off + r);
        pA[12 + i] = *(const uint4*)(Al + a1off + r);
        pW[i]      = *(const uint4*)(Wh + w0off + r);
        pW[4 + i]  = *(const uint4*)(Wl + w0off + r);
        pW[8 + i]  = *(const uint4*)(Wh + w1off + r);
        pW[12 + i] = *(const uint4*)(Wl + w1off + r);
    }

    int ph = 0;
    const int NKT = D_ / 64;
    for (int kt = 0; kt < NKT; ++kt) {
        if (kt > 0) { MBAR_WAIT(mbar, ph); ph ^= 1; }
#pragma unroll
        for (int g = 0; g < 4; ++g) {
            const u32 off = soff + (u32)(g * 4096);
            *(uint4*)(smem + off)          = pA[g];
            *(uint4*)(smem + 16384 + off)  = pA[4 + g];
            *(uint4*)(smem + 32768 + off)  = pA[8 + g];
            *(uint4*)(smem + 49152 + off)  = pA[12 + g];
            *(uint4*)(smem + 65536 + off)  = pW[g];
            *(uint4*)(smem + 81920 + off)  = pW[4 + g];
            *(uint4*)(smem + 98304 + off)  = pW[8 + g];
            *(uint4*)(smem + 114688 + off) = pW[12 + g];
        }
        FENCE_ASYNC();
        __syncthreads();
        if (wid == 0 && elect1()) {
#pragma unroll
            for (int mt = 0; mt < 2; ++mt)
#pragma unroll
                for (int nt = 0; nt < 2; ++nt) {
                    const u32 dst = tmem + (mt * 2 + nt) * 128;
                    const u32 ab = sb + mt * 32768u;
                    const u32 wb = sb + 65536u + nt * 32768u;
#pragma unroll
                    for (int t = 0; t < 3; ++t) {
                        u64 ad = mk_desc(ab + ((t == 2) ? 16384u : 0u));
                        u64 bd = mk_desc(wb + ((t == 1) ? 16384u : 0u));
#pragma unroll
                        for (int k = 0; k < 4; ++k)
                            mma_bf16(dst, ad + k * 2, bd + k * 2, IDESC_BF16,
                                     (kt > 0) || (t > 0) || (k > 0));
                    }
                }
            TC_COMMIT(mbar);
        }
        if (kt + 1 < NKT) {
            const int kk = (kt + 1) * 64;
#pragma unroll
            for (int i = 0; i < 4; ++i) {
                const size_t r = (size_t)(32 * i) * D_ + kk;
                pA[i]      = *(const uint4*)(Ah + a0off + r);
                pA[4 + i]  = *(const uint4*)(Al + a0off + r);
                pA[8 + i]  = *(const uint4*)(Ah + a1off + r);
                pA[12 + i] = *(const uint4*)(Al + a1off + r);
                pW[i]      = *(const uint4*)(Wh + w0off + r);
                pW[4 + i]  = *(const uint4*)(Wl + w0off + r);
                pW[8 + i]  = *(const uint4*)(Wh + w1off + r);
                pW[12 + i] = *(const uint4*)(Wl + w1off + r);
            }
        }
    }
    MBAR_WAIT(mbar, ph);
    TC_FENCE_AFTER();
    return tmem;
}
#endif

// ---------------------------------------------------------------------------
// Fused QKV projection: grid (24, 32). blockIdx.x>>3 selects weight/output.
// ---------------------------------------------------------------------------
__global__ __launch_bounds__(256, 1)
void tc_gemm_qkv(const __nv_bfloat16* __restrict__ Ah, const __nv_bfloat16* __restrict__ Al,
                 const __nv_bfloat16* __restrict__ Wqh, const __nv_bfloat16* __restrict__ Wql,
                 const __nv_bfloat16* __restrict__ Wkh, const __nv_bfloat16* __restrict__ Wkl,
                 const __nv_bfloat16* __restrict__ Wvh, const __nv_bfloat16* __restrict__ Wvl,
                 const int* __restrict__ pos) {
    const int tid = threadIdx.x;
    const int wid = tid >> 5;
    const int lane = tid & 31;
    const int wsel = blockIdx.x >> 3;              // 0=Q 1=K 2=V
    const int n0 = (blockIdx.x & 7) * 256;
    const int m0 = blockIdx.y * 256;
    const int mrow = 32 * (wid & 3) + lane;
    const int tcol = (wid < 4) ? 0 : 64;

    const __nv_bfloat16* Wh = (wsel == 0) ? Wqh : (wsel == 1) ? Wkh : Wvh;
    const __nv_bfloat16* Wl = (wsel == 0) ? Wql : (wsel == 1) ? Wkl : Wvl;
    __nv_bfloat16* Ph = (wsel == 0) ? g_Qh : (wsel == 1) ? g_Kh : g_Vh;
    __nv_bfloat16* Pl = (wsel == 0) ? g_Ql : (wsel == 1) ? g_Kl : g_Vl;

    u32 d[64];

#if TC_EN
    extern __shared__ __align__(1024) char smem[];
    const u32 sb = smem_u32(smem);
    const u32 tmem = gemm_core(smem, sb, Ah, Al, Wh, Wl, m0, n0, tid, wid);
#endif

#pragma unroll
    for (int mt = 0; mt < 2; ++mt)
#pragma unroll
    for (int nt = 0; nt < 2; ++nt) {
        const int m = m0 + mt * 128 + mrow;
        const int n0q = n0 + nt * 128;
#if TC_EN
        TC_LD_32X32B_X32(d,      tmem + (mt * 2 + nt) * 128 + tcol);
        TC_LD_32X32B_X32(d + 32, tmem + (mt * 2 + nt) * 128 + tcol + 32);
        TC_WAIT_LD();
#else
        for (int c = 0; c < 64; ++c) {
            float s = 0.f;
            for (int k = 0; k < D_; ++k) {
                float a = __bfloat162float(Ah[(size_t)m * D_ + k]) +
                          __bfloat162float(Al[(size_t)m * D_ + k]);
                float w = __bfloat162float(Wh[(size_t)(n0q + tcol + c) * D_ + k]) +
                          __bfloat162float(Wl[(size_t)(n0q + tcol + c) * D_ + k]);
                s += a * w;
            }
            d[c] = __float_as_uint(s);
        }
#endif
        const int b = m >> 11;
        const int s = m & (S_ - 1);
        const int bh = b * H_ + (n0q >> 7);
        if (wsel != 2) {  // Q/K: RoPE + planes [bh][s][dh]
            const float fp = (float)pos[s];
#pragma unroll 8
            for (int g = 0; g < 32; ++g) {
                const int j = 2 * g;
                const int jj = tcol + j;
                const float inv = expf(-(float)jj * (9.210340371976184f / 128.0f));
                float sn, cs;
                sincosf(fp * inv, &sn, &cs);
                const float x1 = __uint_as_float(d[j]);
                const float x2 = __uint_as_float(d[j + 1]);
                d[j]     = __float_as_uint(x1 * cs - x2 * sn);
                d[j + 1] = __float_as_uint(x1 * sn + x2 * cs);
            }
            const size_t eb = ((size_t)bh * S_ + s) * DH_ + tcol;
#pragma unroll
            for (int c = 0; c < 64; c += 8) {
                uint4 hi, lo;
                split8(make_float4(__uint_as_float(d[c]),     __uint_as_float(d[c + 1]),
                                   __uint_as_float(d[c + 2]), __uint_as_float(d[c + 3])),
                       make_float4(__uint_as_float(d[c + 4]), __uint_as_float(d[c + 5]),
                                   __uint_as_float(d[c + 6]), __uint_as_float(d[c + 7])),
                       hi, lo);
                *(uint4*)(Ph + eb + c) = hi;
                *(uint4*)(Pl + eb + c) = lo;
            }
        } else {          // V: planes [bh][dh][s]
            const size_t eb = (size_t)bh * DH_ * S_ + s;
#pragma unroll
            for (int j = 0; j < 64; ++j) {
                const int dh = tcol + j;
                float v = __uint_as_float(d[j]);
                __nv_bfloat16 hb = __float2bfloat16(v);
                Ph[eb + (size_t)dh * S_] = hb;
                Pl[eb + (size_t)dh * S_] = __float2bfloat16(v - __bfloat162float(hb));
            }
        }
    }
#if TC_EN
    __syncthreads();
    if (wid == 0) TC_DEALLOC(tmem, 512);
#endif
}

// ---------------------------------------------------------------------------
// Output GEMM: 256x256 tile, plain fp32 write.
// ---------------------------------------------------------------------------
__global__ __launch_bounds__(256, 1)
void tc_gemm_out(const __nv_bfloat16* __restrict__ Ah, const __nv_bfloat16* __restrict__ Al,
                 const __nv_bfloat16* __restrict__ Wh, const __nv_bfloat16* __restrict__ Wl,
                 float* __restrict__ Cf) {
    const int tid = threadIdx.x;
    const int wid = tid >> 5;
    const int lane = tid & 31;
    const int n0 = blockIdx.x * 256;
    const int m0 = blockIdx.y * 256;
    const int mrow = 32 * (wid & 3) + lane;
    const int tcol = (wid < 4) ? 0 : 64;

    u32 d[64];

#if TC_EN
    extern __shared__ __align__(1024) char smem[];
    const u32 sb = smem_u32(smem);
    const u32 tmem = gemm_core(smem, sb, Ah, Al, Wh, Wl, m0, n0, tid, wid);
#endif

#pragma unroll
    for (int mt = 0; mt < 2; ++mt)
#pragma unroll
    for (int nt = 0; nt < 2; ++nt) {
        const int m = m0 + mt * 128 + mrow;
        const int n0q = n0 + nt * 128;
#if TC_EN
        TC_LD_32X32B_X32(d,      tmem + (mt * 2 + nt) * 128 + tcol);
        TC_LD_32X32B_X32(d + 32, tmem + (mt * 2 + nt) * 128 + tcol + 32);
        TC_WAIT_LD();
#else
        for (int c = 0; c < 64; ++c) {
            float s = 0.f;
            for (int k = 0; k < D_; ++k) {
                float a = __bfloat162float(Ah[(size_t)m * D_ + k]) +
                          __bfloat162float(Al[(size_t)m * D_ + k]);
                float w = __bfloat162float(Wh[(size_t)(n0q + tcol + c) * D_ + k]) +
                          __bfloat162float(Wl[(size_t)(n0q + tcol + c) * D_ + k]);
                s += a * w;
            }
            d[c] = __float_as_uint(s);
        }
#endif
        float* dst = Cf + (size_t)m * D_ + n0q + tcol;
#pragma unroll
        for (int c = 0; c < 64; c += 4)
            *(float4*)(dst + c) = make_float4(
                __uint_as_float(d[c]), __uint_as_float(d[c + 1]),
                __uint_as_float(d[c + 2]), __uint_as_float(d[c + 3]));
    }
#if TC_EN
    __syncthreads();
    if (wid == 0) TC_DEALLOC(tmem, 512);
#endif
}

// ---------------------------------------------------------------------------
// Flash attention v2 (round-13 version, part of the 1126us best).
// ---------------------------------------------------------------------------
__global__ __launch_bounds__(256, 1)
void flash_tc() {
    const int tid = threadIdx.x;
    const int bh = blockIdx.x;
    const int qt = 15 - blockIdx.y;
    const int q0 = qt * 128;
    const size_t base = (size_t)bh * S_ * DH_;
    const int b = bh >> 4;
    const int h = bh & 15;
    const float sc = 0.08838834764831845f;

#if TC_EN
    extern __shared__ __align__(1024) char fsm[];
    const u32 sb = smem_u32(fsm);
    const u32 QS = sb;
    const u32 KB = sb + 65536;
    const u32 VB = sb + 131072;
    const u32 PB = sb + 196608;
    const u32 MB_S0 = sb + 229376;
    const u32 MB_S1 = sb + 229384;
    const u32 MB_O  = sb + 229392;
    const u32 TMEMP = sb + 229400;
    float* slf = (float*)(fsm + 229408);

    const int wid = tid >> 5;
    const int lane = tid & 31;
    const int q_rel = 32 * (wid & 3) + lane;
    const int tcol_s = (wid < 4) ? 0 : 32;
    const int tcol_o = (wid < 4) ? 0 : 64;

    if (wid == 0) { TC_ALLOC(TMEMP, 256); TC_RELQ(); }
    if (tid == 0) { MBAR_INIT(MB_S0, 1); MBAR_INIT(MB_S1, 1); MBAR_INIT(MB_O, 1); }
    __syncthreads();
    u32 tmem;
    asm volatile("ld.shared.b32 %0, [%1];" : "=r"(tmem) : "r"(TMEMP));
    const u32 tO = tmem;
    const u32 tS0 = tmem + 128, tS1 = tmem + 192;

    const int c8 = tid & 7;
    const int r0 = (tid >> 3) & 31;
    const u32 soff = swz((u32)(r0 * 128 + c8 * 16));
    const int nst = 2 * (qt + 1);

#pragma unroll
    for (int pl = 0; pl < 2; ++pl) {
        const __nv_bfloat16* qp = pl ? g_Ql : g_Qh;
#pragma unroll
        for (int kb = 0; kb < 2; ++kb)
#pragma unroll
            for (int i = 0; i < 4; ++i) {
                uint4 v = *(const uint4*)(qp + base +
                    (size_t)(q0 + r0 + 32 * i) * DH_ + kb * 64 + c8 * 8);
                *(uint4*)(fsm + pl * 32768 + kb * 16384 + i * 4096 + soff) = v;
            }
    }
#pragma unroll
    for (int jb = 0; jb < 2; ++jb) {
        if (jb < nst) {
            const int jj0 = jb * 64;
#pragma unroll
            for (int pl = 0; pl < 2; ++pl) {
                const __nv_bfloat16* kp = pl ? g_Kl : g_Kh;
#pragma unroll
                for (int kb = 0; kb < 2; ++kb)
#pragma unroll
                    for (int i = 0; i < 2; ++i) {
                        uint4 v = *(const uint4*)(kp + base +
                            (size_t)(jj0 + r0 + 32 * i) * DH_ + kb * 64 + c8 * 8);
                        *(uint4*)(fsm + 65536 + jb * 32768 + pl * 16384 +
                                  kb * 8192 + i * 4096 + soff) = v;
                    }
            }
        }
    }
    {
#pragma unroll
        for (int pl = 0; pl < 2; ++pl) {
            const __nv_bfloat16* vp = pl ? g_Vl : g_Vh;
#pragma unroll
            for (int i = 0; i < 4; ++i) {
                uint4 v = *(const uint4*)(vp + base +
                    (size_t)(r0 + 32 * i) * S_ + 0 + c8 * 8);
                *(uint4*)(fsm + 131072 + pl * 16384 + i * 4096 + soff) = v;
            }
        }
    }
    FENCE_ASYNC();
    __syncthreads();

    if (wid == 0 && elect1()) {
        TC_FENCE_AFTER();
        int first = 1;
#pragma unroll
        for (int t = 0; t < 3; ++t) {
            const int pa = (t == 2) ? 1 : 0;
            const int pb = (t == 1) ? 1 : 0;
#pragma unroll
            for (int kb = 0; kb < 2; ++kb) {
                u64 qd = mk_desc(QS + pa * 32768 + kb * 16384);
                u64 kd = mk_desc(KB + pb * 16384 + kb * 8192);
#pragma unroll
                for (int k = 0; k < 4; ++k) {
                    mma_bf16(tS0, qd + k * 2, kd + k * 2, IDESC_BF16_N64, !first);
                    first = 0;
                }
            }
        }
        TC_COMMIT(MB_S0);
    }

    int ph_s0 = 0, ph_s1 = 0, ph_o = 0;
    float l_part = 0.f;

    for (int j = 0; j < nst; ++j) {
        const int buf = j & 1;
        const int nbuf = buf ^ 1;
        const u32 tSc = buf ? tS1 : tS0;
        const u32 tSn = buf ? tS0 : tS1;

        if (j + 1 < nst && wid == 0 && elect1()) {
            int first = 1;
#pragma unroll
            for (int t = 0; t < 3; ++t) {
                const int pa = (t == 2) ? 1 : 0;
                const int pb = (t == 1) ? 1 : 0;
#pragma unroll
                for (int kb = 0; kb < 2; ++kb) {
                    u64 qd = mk_desc(QS + pa * 32768 + kb * 16384);
                    u64 kd = mk_desc(KB + nbuf * 32768 + pb * 16384 + kb * 8192);
#pragma unroll
                    for (int k = 0; k < 4; ++k) {
                        mma_bf16(tSn, qd + k * 2, kd + k * 2, IDESC_BF16_N64, !first);
                        first = 0;
                    }
                }
            }
            TC_COMMIT(nbuf ? MB_S1 : MB_S0);
        }

        uint4 pK[8], pV[8];
        if (j + 2 < nst) {
            const int jj0 = (j + 2) * 64;
            int ix = 0;
#pragma unroll
            for (int pl = 0; pl < 2; ++pl) {
                const __nv_bfloat16* kp = pl ? g_Kl : g_Kh;
#pragma unroll
                for (int kb = 0; kb < 2; ++kb)
#pragma unroll
                    for (int i = 0; i < 2; ++i)
                        pK[ix++] = *(const uint4*)(kp + base +
                            (size_t)(jj0 + r0 + 32 * i) * DH_ + kb * 64 + c8 * 8);
            }
        }
        if (j + 1 < nst) {
            const int jv0 = (j + 1) * 64;
            int ix = 0;
#pragma unroll
            for (int pl = 0; pl < 2; ++pl) {
                const __nv_bfloat16* vp = pl ? g_Vl : g_Vh;
#pragma unroll
                for (int i = 0; i < 4; ++i)
                    pV[ix++] = *(const uint4*)(vp + base +
                        (size_t)(r0 + 32 * i) * S_ + jv0 + c8 * 8);
            }
        }

        if (j > 0) { MBAR_WAIT(MB_O, ph_o); ph_o ^= 1; }
        if (buf == 0) { MBAR_WAIT(MB_S0, ph_s0); ph_s0 ^= 1; }
        else          { MBAR_WAIT(MB_S1, ph_s1); ph_s1 ^= 1; }
        TC_FENCE_AFTER();

        float p[32];
        TC_LD_32X32B_X32((u32*)p, tSc + tcol_s);
        TC_WAIT_LD();
        TC_FENCE_BEFORE();
        const int thr = q0 + q_rel - 64 * j - tcol_s;
        float lsum = 0.f;
#pragma unroll
        for (int c = 0; c < 32; ++c) {
            float s = __uint_as_float(((u32*)p)[c]);
            float v = (c > thr) ? 0.f : __expf(s * sc);
            p[c] = v; lsum += v;
        }
        l_part += lsum;

#pragma unroll
        for (int c4p = 0; c4p < 4; ++c4p) {
            uint4 hi, lo;
            split8(make_float4(p[c4p*8], p[c4p*8+1], p[c4p*8+2], p[c4p*8+3]),
                   make_float4(p[c4p*8+4], p[c4p*8+5], p[c4p*8+6], p[c4p*8+7]),
                   hi, lo);
            const u32 poff = swz((u32)(q_rel * 128 + tcol_s * 2 + c4p * 16));
            *(uint4*)(fsm + 196608 + poff)         = hi;
            *(uint4*)(fsm + 196608 + 16384 + poff) = lo;
        }
        if (j + 2 < nst) {
            int ix = 0;
#pragma unroll
            for (int pl = 0; pl < 2; ++pl)
#pragma unroll
                for (int kb = 0; kb < 2; ++kb)
#pragma unroll
                    for (int i = 0; i < 2; ++i)
                        *(uint4*)(fsm + 65536 + buf * 32768 + pl * 16384 +
                                  kb * 8192 + i * 4096 + soff) = pK[ix++];
        }
        if (j + 1 < nst) {
            int ix = 0;
#pragma unroll
            for (int pl = 0; pl < 2; ++pl)
#pragma unroll
                for (int i = 0; i < 4; ++i)
                    *(uint4*)(fsm + 131072 + nbuf * 32768 + pl * 16384 +
                              i * 4096 + soff) = pV[ix++];
        }
        FENCE_ASYNC();
        __syncthreads();

        if (wid == 0 && elect1()) {
            TC_FENCE_AFTER();
#pragma unroll
            for (int t = 0; t < 3; ++t) {
                const int pa = (t == 2) ? 1 : 0;
                const int pb = (t == 1) ? 1 : 0;
                u64 pd = mk_desc(PB + pa * 16384);
                u64 vd = mk_desc(VB + buf * 32768 + pb * 16384);
#pragma unroll
                for (int k = 0; k < 4; ++k)
                    mma_bf16(tO, pd + k * 2, vd + k * 2, IDESC_BF16,
                             (j > 0) || (t > 0) || (k > 0));
            }
            TC_COMMIT(MB_O);
        }
    }

    MBAR_WAIT(MB_O, ph_o);
    TC_FENCE_AFTER();

    slf[(wid < 4 ? 0 : 128) + q_rel] = l_part;
    __syncthreads();
    const float invl = 1.0f / (slf[q_rel] + slf[128 + q_rel]);

    float o[64];
    TC_LD_32X32B_X32((u32*)o,      tO + tcol_o);
    TC_LD_32X32B_X32((u32*)o + 32, tO + tcol_o + 32);
    TC_WAIT_LD();
    TC_FENCE_BEFORE();
    __syncthreads();
    if (wid == 0) TC_DEALLOC(tmem, 256);

    const size_t eb = (size_t)(b * S_ + q0 + q_rel) * D_ + h * DH_ + tcol_o;
#pragma unroll
    for (int g8 = 0; g8 < 8; ++g8) {
        float f[8];
#pragma unroll
        for (int j = 0; j < 8; ++j) f[j] = o[g8 * 8 + j] * invl;
        uint4 hi, lo;
        split8(make_float4(f[0], f[1], f[2], f[3]),
               make_float4(f[4], f[5], f[6], f[7]), hi, lo);
        *(uint4*)(g_ATh + eb + g8 * 8) = hi;
        *(uint4*)(g_ATl + eb + g8 * 8) = lo;
    }
#else
    if (tid < 128) {
        const int q = q0 + tid;
        float O[128];
        for (int d0 = 0; d0 < 128; ++d0) O[d0] = 0.f;
        float l = 0.f;
        for (int c = 0; c <= q; ++c) {
            float s = 0.f;
            for (int d0 = 0; d0 < 128; ++d0) {
                float qv = __bfloat162float(g_Qh[base + (size_t)q * DH_ + d0]) +
                           __bfloat162float(g_Ql[base + (size_t)q * DH_ + d0]);
                float kv = __bfloat162float(g_Kh[base + (size_t)c * DH_ + d0]) +
                           __bfloat162float(g_Kl[base + (size_t)c * DH_ + d0]);
                s += qv * kv;
            }
            float v = __expf(s * sc);
            l += v;
            for (int d0 = 0; d0 < 128; ++d0) {
                float vv = __bfloat162float(g_Vh[base + (size_t)d0 * S_ + c]) +
                           __bfloat162float(g_Vl[base + (size_t)d0 * S_ + c]);
                O[d0] += v * vv;
            }
        }
        const size_t eb = (size_t)(b * S_ + q) * D_ + h * DH_;
        for (int d0 = 0; d0 < 128; ++d0) {
            float v = O[d0] / l;
            __nv_bfloat16 hb = __float2bfloat16(v);
            g_ATh[eb + d0] = hb;
            g_ATl[eb + d0] = __float2bfloat16(v - __bfloat162float(hb));
        }
    }
#endif
}

// ---------------------------------------------------------------------------
extern "C" void kernel_launch(void* const* d_in, const int* in_sizes, int n_in,
                              void* d_out, int out_size) {
    const float* x  = (const float*)d_in[0];
    const int*   tp = (const int*)d_in[1];
    const float* wq = (const float*)d_in[2];
    const float* wk = (const float*)d_in[3];
    const float* wv = (const float*)d_in[4];
    const float* wo = (const float*)d_in[5];
    float* out = (float*)d_out;

    __nv_bfloat16 *Xh, *Xl, *Wqh, *Wql, *Wkh, *Wkl, *Wvh, *Wvl, *Woh, *Wol;
    __nv_bfloat16 *ATh, *ATl;
    cudaGetSymbolAddress((void**)&Xh,  g_Xh);  cudaGetSymbolAddress((void**)&Xl,  g_Xl);
    cudaGetSymbolAddress((void**)&Wqh, g_Wqh); cudaGetSymbolAddress((void**)&Wql, g_Wql);
    cudaGetSymbolAddress((void**)&Wkh, g_Wkh); cudaGetSymbolAddress((void**)&Wkl, g_Wkl);
    cudaGetSymbolAddress((void**)&Wvh, g_Wvh); cudaGetSymbolAddress((void**)&Wvl, g_Wvl);
    cudaGetSymbolAddress((void**)&Woh, g_Woh); cudaGetSymbolAddress((void**)&Wol, g_Wol);
    cudaGetSymbolAddress((void**)&ATh, g_ATh); cudaGetSymbolAddress((void**)&ATl, g_ATl);

    const int smem_gemm = 131072 + 64;
    cudaFuncSetAttribute(tc_gemm_qkv, cudaFuncAttributeMaxDynamicSharedMemorySize, smem_gemm);
    cudaFuncSetAttribute(tc_gemm_out, cudaFuncAttributeMaxDynamicSharedMemorySize, smem_gemm);

    const int smem_flash = 229376 + 32 + 1024;
    cudaFuncSetAttribute(flash_tc,
                         cudaFuncAttributeMaxDynamicSharedMemorySize, smem_flash);

    const int ntot = (T_ * D_) / 8 + 4 * ((D_ * D_) / 8);
    split_all<<<ntot / 256, 256>>>(x, wq, wk, wv, wo);

    tc_gemm_qkv<<<dim3(24, T_ / 256), 256, smem_gemm>>>(
        Xh, Xl, Wqh, Wql, Wkh, Wkl, Wvh, Wvl, tp);

    flash_tc<<<dim3(NB_ * H_, S_ / 128), 256, smem_flash>>>();

    tc_gemm_out<<<dim3(D_ / 256, T_ / 256), 256, smem_gemm>>>(
        ATh, ATl, Woh, Wol, out);
}